// round 12
// baseline (speedup 1.0000x reference)
#include <cuda_runtime.h>
#include <cstdint>
#include <cstddef>

#define E_DIM  1024
#define NHEAD  16
#define HDIM   64
#define BATCH  2
#define SEQ_Q  1024
#define SEQ_KV 4096
#define LN_EPS 1e-5f
#define SM_SHIFT 8.0f
#define IDXCAP 4160

// ---------------- scratch (no allocations allowed) ----------------
__device__ float g_Qp[(size_t)BATCH * NHEAD * SEQ_Q * HDIM];     // [B,H,SQ,D]  (tf32-rounded)
__device__ float g_Kp[(size_t)BATCH * NHEAD * SEQ_KV * HDIM];    // compact [B,H,s,D]
__device__ float g_Vp[(size_t)BATCH * NHEAD * SEQ_KV * HDIM];    // compact TRANSPOSED [B,H,D,s]
__device__ float g_attn[(size_t)BATCH * SEQ_Q * E_DIM];          // [B*SQ, E]
__device__ float g_proj[(size_t)BATCH * SEQ_Q * E_DIM];          // [B*SQ, E]
__device__ float g_qr [(size_t)BATCH * SEQ_Q * E_DIM];           // rounded query
__device__ float g_kvr[(size_t)BATCH * SEQ_KV * E_DIM];          // rounded key_value
__device__ float g_w  [(size_t)4 * E_DIM * E_DIM];               // rounded Wq,Wk,Wv,Wo
__device__ int   g_idx [BATCH][IDXCAP];
__device__ float g_bias[BATCH][IDXCAP];
__device__ int   g_ntiles[BATCH];

// ---------------- helpers ----------------
__device__ __forceinline__ float f2tff(float f) {
    unsigned u;
    asm("cvt.rna.tf32.f32 %0, %1;" : "=r"(u) : "f"(f));
    return __uint_as_float(u);
}

__device__ __forceinline__ void mma8(float* c, const unsigned* a, unsigned b0, unsigned b1) {
    asm volatile(
        "mma.sync.aligned.m16n8k8.row.col.f32.tf32.tf32.f32 "
        "{%0,%1,%2,%3}, {%4,%5,%6,%7}, {%8,%9}, {%0,%1,%2,%3};\n"
        : "+f"(c[0]), "+f"(c[1]), "+f"(c[2]), "+f"(c[3])
        : "r"(a[0]), "r"(a[1]), "r"(a[2]), "r"(a[3]), "r"(b0), "r"(b1));
}

__device__ __forceinline__ void ldsm4(unsigned* r, uint32_t addr) {
    asm volatile("ldmatrix.sync.aligned.m8n8.x4.shared.b16 {%0,%1,%2,%3}, [%4];"
                 : "=r"(r[0]), "=r"(r[1]), "=r"(r[2]), "=r"(r[3]) : "r"(addr));
}

__device__ __forceinline__ void cpasync16(const float* dst, const float* src) {
    uint32_t d = (uint32_t)__cvta_generic_to_shared(dst);
    asm volatile("cp.async.cg.shared.global [%0], [%1], 16;" :: "r"(d), "l"(src));
}
#define CP_COMMIT() asm volatile("cp.async.commit_group;" ::: "memory")
#define CP_WAIT(n)  asm volatile("cp.async.wait_group %0;" :: "n"(n) : "memory")

// ---------------- pre-round kernels ----------------
__global__ void __launch_bounds__(256) round_one(const float* __restrict__ in,
                                                 float* __restrict__ out, int n4) {
    int i = blockIdx.x * 256 + threadIdx.x;
    if (i < n4) {
        float4 v = ((const float4*)in)[i];
        float4 r;
        r.x = f2tff(v.x); r.y = f2tff(v.y); r.z = f2tff(v.z); r.w = f2tff(v.w);
        ((float4*)out)[i] = r;
    }
}

__global__ void __launch_bounds__(256) round_w(const float* __restrict__ a,
                                               const float* __restrict__ b,
                                               const float* __restrict__ c,
                                               const float* __restrict__ d,
                                               float* __restrict__ o) {
    const float* in = (blockIdx.y == 0) ? a : (blockIdx.y == 1) ? b : (blockIdx.y == 2) ? c : d;
    float* out = o + (size_t)blockIdx.y * E_DIM * E_DIM;
    int i = blockIdx.x * 256 + threadIdx.x;
    float4 v = ((const float4*)in)[i];
    float4 r;
    r.x = f2tff(v.x); r.y = f2tff(v.y); r.z = f2tff(v.z); r.w = f2tff(v.w);
    ((float4*)out)[i] = r;
}

// ---------------- mask compaction ----------------
__global__ void __launch_bounds__(1024) compact_kernel(const int* __restrict__ mask) {
    const int b   = blockIdx.x;
    const int tid = threadIdx.x;
    const int lane = tid & 31, warp = tid >> 5;
    const int* m = mask + (size_t)b * SEQ_KV;
    __shared__ int warpSums[32];

    int v[4];
    int base = tid * 4;
    int cnt = 0;
#pragma unroll
    for (int i = 0; i < 4; i++) { v[i] = (m[base + i] != 0); cnt += v[i]; }

    int x = cnt;
#pragma unroll
    for (int off = 1; off < 32; off <<= 1) {
        int y = __shfl_up_sync(0xffffffffu, x, off);
        if (lane >= off) x += y;
    }
    if (lane == 31) warpSums[warp] = x;
    __syncthreads();
    if (warp == 0) {
        int wsum = warpSums[lane];
#pragma unroll
        for (int off = 1; off < 32; off <<= 1) {
            int y = __shfl_up_sync(0xffffffffu, wsum, off);
            if (lane >= off) wsum += y;
        }
        warpSums[lane] = wsum;
    }
    __syncthreads();
    int warpBase = (warp == 0) ? 0 : warpSums[warp - 1];
    int pos = warpBase + x - cnt;
#pragma unroll
    for (int i = 0; i < 4; i++) {
        if (v[i]) {
            g_idx[b][pos]  = base + i;
            g_bias[b][pos] = -SM_SHIFT;
            pos++;
        }
    }
    __syncthreads();
    int total  = warpSums[31];
    int padded = (total + 63) & ~63;
    for (int j = total + tid; j < padded; j += 1024) {
        g_idx[b][j]  = 0;
        g_bias[b][j] = -3.0e38f;
    }
    if (tid == 0) g_ntiles[b] = padded >> 6;
}

// ---------------- high-occupancy GEMM: BM=64, BN=64, warp tile 16x32 ----------------
// 8 warps (4 along M x 2 along N), 2-stage cp.async, static smem 36.9KB, 4 CTAs/SM.
template <bool PERM>
__device__ __forceinline__ void storeC(float* __restrict__ C, int r, int c, float2 v, int S) {
    if (PERM) {
        int b = r / S;
        int s = r - b * S;
        int h = c >> 6;
        int d = c & 63;
        *(float2*)(C + (((size_t)b * NHEAD + h) * S + s) * HDIM + d) = v;
    } else {
        *(float2*)(C + (size_t)r * E_DIM + c) = v;
    }
}

#define G2_STG (64 * 36)   // floats per stage (A or B)

template <bool PERM>
__global__ void __launch_bounds__(256, 4) gemm_tf32_kernel(
    const float* __restrict__ A, const float* __restrict__ W,
    const float* __restrict__ bias, float* __restrict__ C,
    int S, float outScale)
{
    __shared__ float sm[4 * G2_STG];   // As[2] then Bs[2]
    float* As = sm;
    float* Bs = sm + 2 * G2_STG;

    const int tid  = threadIdx.x;
    const int lane = tid & 31;
    const int warp = tid >> 5;
    const int lq   = lane >> 2;
    const int kq   = lane & 3;
    const int bm   = blockIdx.x * 64;
    const int bn   = blockIdx.y * 64;
    const int wm   = (warp & 3) * 16;
    const int wn   = (warp >> 2) * 32;

    auto issue = [&](int kt, int s) {
#pragma unroll
        for (int p = 0; p < 2; p++) {
            int i4  = p * 256 + tid;
            int row = i4 >> 3;
            int c4  = i4 & 7;
            cpasync16(As + s * G2_STG + row * 36 + c4 * 4,
                      A + (size_t)(bm + row) * E_DIM + kt * 32 + c4 * 4);
            cpasync16(Bs + s * G2_STG + row * 36 + c4 * 4,
                      W + (size_t)(bn + row) * E_DIM + kt * 32 + c4 * 4);
        }
        CP_COMMIT();
    };

    float acc[4][4];
#pragma unroll
    for (int nt = 0; nt < 4; nt++)
#pragma unroll
        for (int r = 0; r < 4; r++) acc[nt][r] = 0.0f;

    const int aOff = (wm + (lane & 15)) * 36 + ((lane >> 4) << 2);
    const int bOff = (wn + (lane & 7) + ((lane & 16) >> 1)) * 36 + ((lane & 8) >> 1);

    issue(0, 0);
    issue(1, 1);

#pragma unroll 1
    for (int kt = 0; kt < 32; kt++) {
        if (kt < 31) { CP_WAIT(1); } else { CP_WAIT(0); }
        __syncthreads();
        uint32_t aB = (uint32_t)__cvta_generic_to_shared(As + (kt & 1) * G2_STG);
        uint32_t bB = (uint32_t)__cvta_generic_to_shared(Bs + (kt & 1) * G2_STG);

#pragma unroll
        for (int ks = 0; ks < 4; ks++) {
            const int k0 = ks * 8;
            unsigned af[4];
            ldsm4(af, aB + 4u * (aOff + k0));
#pragma unroll
            for (int np = 0; np < 2; np++) {
                unsigned bf[4];
                ldsm4(bf, bB + 4u * (bOff + np * 16 * 36 + k0));
                mma8(acc[2 * np],     af, bf[0], bf[1]);
                mma8(acc[2 * np + 1], af, bf[2], bf[3]);
            }
        }
        __syncthreads();
        if (kt + 2 < 32) issue(kt + 2, kt & 1);
    }

    // epilogue: 16 rows x 32 cols per warp
    int rA = bm + wm + lq;
#pragma unroll
    for (int nt = 0; nt < 4; nt++) {
        int c0 = bn + wn + nt * 8 + 2 * kq;
        float b0 = bias[c0], b1 = bias[c0 + 1];
        float v0 = (acc[nt][0] + b0) * outScale;
        float v1 = (acc[nt][1] + b1) * outScale;
        float v2 = (acc[nt][2] + b0) * outScale;
        float v3 = (acc[nt][3] + b1) * outScale;
        if (PERM) { v0 = f2tff(v0); v1 = f2tff(v1); v2 = f2tff(v2); v3 = f2tff(v3); }
        storeC<PERM>(C, rA, c0, make_float2(v0, v1), S);
        storeC<PERM>(C, rA + 8, c0, make_float2(v2, v3), S);
    }
}

// ---------------- KV GEMM with row gather + early exit (BN=64 variant) ----------------
// grid.x = B*64 row-tiles, grid.y = E/64. TRANS=false -> K [B,H,s,D]; true -> V [B,H,D,s].
template <bool TRANS>
__global__ void __launch_bounds__(256, 4) gemm_kv_kernel(
    const float* __restrict__ A, const float* __restrict__ W,
    const float* __restrict__ bias, float* __restrict__ C)
{
    const int tile = blockIdx.x;
    const int b    = tile >> 6;
    const int lt   = tile & 63;
    if (lt >= g_ntiles[b]) return;

    __shared__ float sm[4 * G2_STG];
    __shared__ int sIdx[64];
    float* As = sm;
    float* Bs = sm + 2 * G2_STG;

    const int tid  = threadIdx.x;
    const int lane = tid & 31;
    const int warp = tid >> 5;
    const int lq   = lane >> 2;
    const int kq   = lane & 3;
    const int bn   = blockIdx.y * 64;
    const int wm   = (warp & 3) * 16;
    const int wn   = (warp >> 2) * 32;

    if (tid < 64) sIdx[tid] = g_idx[b][lt * 64 + tid];
    __syncthreads();

    const float* Ab = A + (size_t)b * SEQ_KV * E_DIM;

    auto issue = [&](int kt, int s) {
#pragma unroll
        for (int p = 0; p < 2; p++) {
            int i4  = p * 256 + tid;
            int row = i4 >> 3;
            int c4  = i4 & 7;
            cpasync16(As + s * G2_STG + row * 36 + c4 * 4,
                      Ab + (size_t)sIdx[row] * E_DIM + kt * 32 + c4 * 4);
            cpasync16(Bs + s * G2_STG + row * 36 + c4 * 4,
                      W + (size_t)(bn + row) * E_DIM + kt * 32 + c4 * 4);
        }
        CP_COMMIT();
    };

    float acc[4][4];
#pragma unroll
    for (int nt = 0; nt < 4; nt++)
#pragma unroll
        for (int r = 0; r < 4; r++) acc[nt][r] = 0.0f;

    const int aOff = (wm + (lane & 15)) * 36 + ((lane >> 4) << 2);
    const int bOff = (wn + (lane & 7) + ((lane & 16) >> 1)) * 36 + ((lane & 8) >> 1);

    issue(0, 0);
    issue(1, 1);

#pragma unroll 1
    for (int kt = 0; kt < 32; kt++) {
        if (kt < 31) { CP_WAIT(1); } else { CP_WAIT(0); }
        __syncthreads();
        uint32_t aB = (uint32_t)__cvta_generic_to_shared(As + (kt & 1) * G2_STG);
        uint32_t bB = (uint32_t)__cvta_generic_to_shared(Bs + (kt & 1) * G2_STG);

#pragma unroll
        for (int ks = 0; ks < 4; ks++) {
            const int k0 = ks * 8;
            unsigned af[4];
            ldsm4(af, aB + 4u * (aOff + k0));
#pragma unroll
            for (int np = 0; np < 2; np++) {
                unsigned bf[4];
                ldsm4(bf, bB + 4u * (bOff + np * 16 * 36 + k0));
                mma8(acc[2 * np],     af, bf[0], bf[1]);
                mma8(acc[2 * np + 1], af, bf[2], bf[3]);
            }
        }
        __syncthreads();
        if (kt + 2 < 32) issue(kt + 2, kt & 1);
    }

    int sRow = lt * 64 + wm + lq;
#pragma unroll
    for (int nt = 0; nt < 4; nt++) {
        int c0 = bn + wn + nt * 8 + 2 * kq;
        int h = c0 >> 6, d = c0 & 63;
        float b0 = bias[c0], b1 = bias[c0 + 1];
        float v0 = f2tff(acc[nt][0] + b0);
        float v1 = f2tff(acc[nt][1] + b1);
        float v2 = f2tff(acc[nt][2] + b0);
        float v3 = f2tff(acc[nt][3] + b1);
        if (TRANS) {
            float* base = C + (((size_t)b * NHEAD + h) * HDIM) * SEQ_KV;
            base[(size_t)d * SEQ_KV + sRow]           = v0;
            base[(size_t)(d + 1) * SEQ_KV + sRow]     = v1;
            base[(size_t)d * SEQ_KV + sRow + 8]       = v2;
            base[(size_t)(d + 1) * SEQ_KV + sRow + 8] = v3;
        } else {
            *(float2*)(C + (((size_t)b * NHEAD + h) * SEQ_KV + sRow) * HDIM + d) =
                make_float2(v0, v1);
            *(float2*)(C + (((size_t)b * NHEAD + h) * SEQ_KV + sRow + 8) * HDIM + d) =
                make_float2(v2, v3);
        }
    }
}

// ---------------- Flash attention over compact keys (unchanged round-11 winner) ----------------
#define QSTR 68
#define KSTR 68
#define VSTR 68
#define KTILE_F (64 * KSTR)
#define VTILE_F (64 * VSTR)
#define QOFF 0
#define KOFF (128 * QSTR)
#define VOFF (KOFF + 2 * KTILE_F)
#define MOFF (VOFF + 2 * VTILE_F)
#define ATT_SMEM_BYTES ((MOFF + 128) * 4)

__global__ void __launch_bounds__(128) attn_kernel()
{
    extern __shared__ float sm[];

    const int tid  = threadIdx.x;
    const int lane = tid & 31;
    const int warp = tid >> 5;
    const int lq   = lane >> 2;
    const int kq   = lane & 3;
    const int qt = blockIdx.x, h = blockIdx.y, b = blockIdx.z;

    const int nt = g_ntiles[b];

    const float* Qg = g_Qp + (((size_t)b * NHEAD + h) * SEQ_Q + qt * 128) * HDIM;
    const float* Kg = g_Kp + ((size_t)b * NHEAD + h) * SEQ_KV * HDIM;
    const float* Vg = g_Vp + ((size_t)b * NHEAD + h) * (size_t)HDIM * SEQ_KV;

#pragma unroll
    for (int p = 0; p < 16; p++) {
        int i4  = p * 128 + tid;
        int row = i4 >> 4;
        int c4  = i4 & 15;
        cpasync16(sm + QOFF + row * QSTR + c4 * 4, Qg + row * HDIM + c4 * 4);
    }
    CP_COMMIT();
    CP_WAIT(0);
    __syncthreads();

    const int r0 = warp * 32;
    unsigned qf[2][8][4];
#pragma unroll
    for (int rb = 0; rb < 2; rb++)
#pragma unroll
        for (int ks = 0; ks < 8; ks++) {
            int rr = r0 + rb * 16;
            qf[rb][ks][0] = __float_as_uint(sm[QOFF + (rr + lq) * QSTR + ks * 8 + kq]);
            qf[rb][ks][1] = __float_as_uint(sm[QOFF + (rr + 8 + lq) * QSTR + ks * 8 + kq]);
            qf[rb][ks][2] = __float_as_uint(sm[QOFF + (rr + lq) * QSTR + ks * 8 + 4 + kq]);
            qf[rb][ks][3] = __float_as_uint(sm[QOFF + (rr + 8 + lq) * QSTR + ks * 8 + 4 + kq]);
        }
    __syncthreads();

    auto issue = [&](int kt, int s) {
        const float* kp = Kg + (size_t)kt * 64 * HDIM;
        const float* vp = Vg + (size_t)kt * 64;
#pragma unroll
        for (int p = 0; p < 8; p++) {
            int i4  = p * 128 + tid;
            int row = i4 >> 4;
            int c4  = i4 & 15;
            cpasync16(sm + KOFF + s * KTILE_F + row * KSTR + c4 * 4, kp + row * HDIM + c4 * 4);
            cpasync16(sm + VOFF + s * VTILE_F + row * VSTR + c4 * 4,
                      vp + (size_t)row * SEQ_KV + c4 * 4);
        }
        if (tid < 64) sm[MOFF + s * 64 + tid] = g_bias[b][kt * 64 + tid];
        CP_COMMIT();
    };

    float o[2][8][4];
#pragma unroll
    for (int rb = 0; rb < 2; rb++)
#pragma unroll
        for (int ntl = 0; ntl < 8; ntl++)
#pragma unroll
            for (int r = 0; r < 4; r++) o[rb][ntl][r] = 0.0f;

    float lAcc[2][2] = {{0.0f, 0.0f}, {0.0f, 0.0f}};

    issue(0, 0);
    if (nt > 1) issue(1, 1);

    const int kOffBase = ((lane & 7) + ((lane & 16) >> 1)) * KSTR + ((lane & 8) >> 1);
    const int vOffBase = ((lane & 7) + ((lane & 16) >> 1)) * VSTR + ((lane & 8) >> 1);
    const int pOffBase = (r0 + (lane & 15)) * QSTR + ((lane >> 4) << 2);

#pragma unroll 1
    for (int kt = 0; kt < nt; kt++) {
        if (kt + 1 < nt) { CP_WAIT(1); } else { CP_WAIT(0); }
        __syncthreads();
        const int s = kt & 1;
        const float* msk = sm + MOFF + s * 64;
        uint32_t kB = (uint32_t)__cvta_generic_to_shared(sm + KOFF + s * KTILE_F);
        uint32_t vB = (uint32_t)__cvta_generic_to_shared(sm + VOFF + s * VTILE_F);
        uint32_t pB = (uint32_t)__cvta_generic_to_shared(sm + QOFF);

        float sacc[2][8][4];
#pragma unroll
        for (int rb = 0; rb < 2; rb++)
#pragma unroll
            for (int ntl = 0; ntl < 8; ntl++)
#pragma unroll
                for (int r = 0; r < 4; r++) sacc[rb][ntl][r] = 0.0f;

#pragma unroll
        for (int ks = 0; ks < 8; ks++) {
            const int k0 = ks * 8;
#pragma unroll
            for (int np = 0; np < 4; np++) {
                unsigned kf[4];
                ldsm4(kf, kB + 4u * (kOffBase + np * 16 * KSTR + k0));
                mma8(sacc[0][2 * np],     qf[0][ks], kf[0], kf[1]);
                mma8(sacc[1][2 * np],     qf[1][ks], kf[0], kf[1]);
                mma8(sacc[0][2 * np + 1], qf[0][ks], kf[2], kf[3]);
                mma8(sacc[1][2 * np + 1], qf[1][ks], kf[2], kf[3]);
            }
        }

#pragma unroll
        for (int ntl = 0; ntl < 8; ntl++) {
            float m0 = msk[ntl * 8 + 2 * kq];
            float m1 = msk[ntl * 8 + 2 * kq + 1];
#pragma unroll
            for (int rb = 0; rb < 2; rb++) {
                float p0 = f2tff(__expf(sacc[rb][ntl][0] + m0));
                float p1 = f2tff(__expf(sacc[rb][ntl][1] + m1));
                float p2 = f2tff(__expf(sacc[rb][ntl][2] + m0));
                float p3 = f2tff(__expf(sacc[rb][ntl][3] + m1));
                lAcc[rb][0] += p0 + p1;
                lAcc[rb][1] += p2 + p3;
                int rr = r0 + rb * 16;
                *(float2*)(sm + QOFF + (rr + lq) * QSTR + ntl * 8 + 2 * kq)     = make_float2(p0, p1);
                *(float2*)(sm + QOFF + (rr + 8 + lq) * QSTR + ntl * 8 + 2 * kq) = make_float2(p2, p3);
            }
        }
        __syncwarp();

#pragma unroll
        for (int ks = 0; ks < 8; ks++) {
            const int k0 = ks * 8;
            unsigned pf[2][4];
            ldsm4(pf[0], pB + 4u * (pOffBase + k0));
            ldsm4(pf[1], pB + 4u * (pOffBase + 16 * QSTR + k0));
#pragma unroll
            for (int np = 0; np < 4; np++) {
                unsigned vf[4];
                ldsm4(vf, vB + 4u * (vOffBase + np * 16 * VSTR + k0));
                mma8(o[0][2 * np],     pf[0], vf[0], vf[1]);
                mma8(o[1][2 * np],     pf[1], vf[0], vf[1]);
                mma8(o[0][2 * np + 1], pf[0], vf[2], vf[3]);
                mma8(o[1][2 * np + 1], pf[1], vf[2], vf[3]);
            }
        }
        __syncthreads();
        if (kt + 2 < nt) issue(kt + 2, s);
    }

#pragma unroll
    for (int rb = 0; rb < 2; rb++)
#pragma unroll
        for (int j = 0; j < 2; j++) {
            lAcc[rb][j] += __shfl_xor_sync(0xffffffffu, lAcc[rb][j], 1);
            lAcc[rb][j] += __shfl_xor_sync(0xffffffffu, lAcc[rb][j], 2);
        }

    float* outBase = g_attn + (size_t)b * SEQ_Q * E_DIM;
#pragma unroll
    for (int rb = 0; rb < 2; rb++) {
        float rA = 1.0f / lAcc[rb][0], rB = 1.0f / lAcc[rb][1];
        int qA = qt * 128 + r0 + rb * 16 + lq;
#pragma unroll
        for (int ntl = 0; ntl < 8; ntl++) {
            int c = h * HDIM + ntl * 8 + 2 * kq;
            *(float2*)(outBase + (size_t)qA * E_DIM + c) =
                make_float2(f2tff(o[rb][ntl][0] * rA), f2tff(o[rb][ntl][1] * rA));
            *(float2*)(outBase + (size_t)(qA + 8) * E_DIM + c) =
                make_float2(f2tff(o[rb][ntl][2] * rB), f2tff(o[rb][ntl][3] * rB));
        }
    }
}

// ---------------- residual + LayerNorm ----------------
__global__ void __launch_bounds__(256) ln_kernel(
    const float* __restrict__ query, const float* __restrict__ proj,
    const float* __restrict__ gamma, const float* __restrict__ beta,
    float* __restrict__ out)
{
    __shared__ float rs[8], rs2[8];
    const int row = blockIdx.x, tid = threadIdx.x;
    const int lane = tid & 31, warp = tid >> 5;
    const size_t base = (size_t)row * E_DIM + tid * 4;

    float4 q = *(const float4*)(query + base);
    float4 p = *(const float4*)(proj + base);
    float x0 = q.x + p.x, x1 = q.y + p.y, x2 = q.z + p.z, x3 = q.w + p.w;
    float s  = x0 + x1 + x2 + x3;
    float s2 = x0 * x0 + x1 * x1 + x2 * x2 + x3 * x3;
#pragma unroll
    for (int off = 16; off; off >>= 1) {
        s  += __shfl_xor_sync(0xffffffffu, s, off);
        s2 += __shfl_xor_sync(0xffffffffu, s2, off);
    }
    if (lane == 0) { rs[warp] = s; rs2[warp] = s2; }
    __syncthreads();
    s = 0.0f; s2 = 0.0f;
#pragma unroll
    for (int i = 0; i < 8; i++) { s += rs[i]; s2 += rs2[i]; }

    float mean = s * (1.0f / E_DIM);
    float var  = s2 * (1.0f / E_DIM) - mean * mean;
    float rstd = rsqrtf(var + LN_EPS);

    float4 g  = *(const float4*)(gamma + tid * 4);
    float4 bb = *(const float4*)(beta + tid * 4);
    float4 r;
    r.x = (x0 - mean) * rstd * g.x + bb.x;
    r.y = (x1 - mean) * rstd * g.y + bb.y;
    r.z = (x2 - mean) * rstd * g.z + bb.z;
    r.w = (x3 - mean) * rstd * g.w + bb.w;
    *(float4*)(out + base) = r;
}

// ---------------- launch ----------------
extern "C" void kernel_launch(void* const* d_in, const int* in_sizes, int n_in,
                              void* d_out, int out_size)
{
    const float* query     = (const float*)d_in[0];
    const float* key_value = (const float*)d_in[1];
    const int*   kvmask    = (const int*)d_in[2];
    const float* Wq = (const float*)d_in[3];
    const float* bq = (const float*)d_in[4];
    const float* Wk = (const float*)d_in[5];
    const float* bk = (const float*)d_in[6];
    const float* Wv = (const float*)d_in[7];
    const float* bv = (const float*)d_in[8];
    const float* Wo = (const float*)d_in[9];
    const float* bo = (const float*)d_in[10];
    const float* gamma = (const float*)d_in[11];
    const float* beta  = (const float*)d_in[12];
    float* out = (float*)d_out;

    float *Qp, *Kp, *Vp, *attn, *proj, *qr, *kvr, *w;
    cudaGetSymbolAddress((void**)&Qp, g_Qp);
    cudaGetSymbolAddress((void**)&Kp, g_Kp);
    cudaGetSymbolAddress((void**)&Vp, g_Vp);
    cudaGetSymbolAddress((void**)&attn, g_attn);
    cudaGetSymbolAddress((void**)&proj, g_proj);
    cudaGetSymbolAddress((void**)&qr, g_qr);
    cudaGetSymbolAddress((void**)&kvr, g_kvr);
    cudaGetSymbolAddress((void**)&w, g_w);

    cudaFuncSetAttribute(attn_kernel,
                         cudaFuncAttributeMaxDynamicSharedMemorySize, ATT_SMEM_BYTES);

    // mask compaction + pre-round
    compact_kernel<<<BATCH, 1024>>>(kvmask);
    round_one<<<(BATCH * SEQ_Q * E_DIM / 4 + 255) / 256, 256>>>(query, qr, BATCH * SEQ_Q * E_DIM / 4);
    round_one<<<(BATCH * SEQ_KV * E_DIM / 4 + 255) / 256, 256>>>(key_value, kvr, BATCH * SEQ_KV * E_DIM / 4);
    round_w<<<dim3(E_DIM * E_DIM / 4 / 256, 4), 256>>>(Wq, Wk, Wv, Wo, w);

    // projections (all BN=64 high-occupancy)
    gemm_tf32_kernel<true><<<dim3(BATCH * SEQ_Q / 64, E_DIM / 64), 256>>>(
        qr, w, bq, Qp, SEQ_Q, 0.125f);
    gemm_kv_kernel<false><<<dim3(BATCH * 64, E_DIM / 64), 256>>>(
        kvr, w + (size_t)E_DIM * E_DIM, bk, Kp);
    gemm_kv_kernel<true><<<dim3(BATCH * 64, E_DIM / 64), 256>>>(
        kvr, w + 2 * (size_t)E_DIM * E_DIM, bv, Vp);

    // attention over compact keys
    attn_kernel<<<dim3(SEQ_Q / 128, NHEAD, BATCH), 128, ATT_SMEM_BYTES>>>();

    // output projection
    gemm_tf32_kernel<false><<<dim3(BATCH * SEQ_Q / 64, E_DIM / 64), 256>>>(
        attn, w + 3 * (size_t)E_DIM * E_DIM, bo, proj, SEQ_Q, 1.0f);

    // residual + LN
    ln_kernel<<<BATCH * SEQ_Q, 256>>>(query, proj, gamma, beta, out);
}

// round 14
// speedup vs baseline: 1.8732x; 1.8732x over previous
#include <cuda_runtime.h>
#include <cuda_fp16.h>
#include <cstdint>
#include <cstddef>

#define E_DIM  1024
#define NHEAD  16
#define HDIM   64
#define BATCH  2
#define SEQ_Q  1024
#define SEQ_KV 4096
#define LN_EPS 1e-5f
#define SM_SHIFT 8.0f
#define IDXCAP 4160

// ---------------- scratch (no allocations allowed) ----------------
__device__ __half g_qh  [(size_t)BATCH * SEQ_Q * E_DIM];          // query fp16
__device__ __half g_kvc [(size_t)BATCH * IDXCAP * E_DIM];         // compact gathered kv fp16
__device__ __half g_wh  [(size_t)4 * E_DIM * E_DIM];              // Wq,Wk,Wv,Wo fp16
__device__ __half g_Qp  [(size_t)BATCH * NHEAD * SEQ_Q * HDIM];   // [B,H,SQ,D] fp16 (x0.125)
__device__ __half g_Kp  [(size_t)BATCH * NHEAD * SEQ_KV * HDIM];  // compact [B,H,s,D] fp16
__device__ __half g_Vp  [(size_t)BATCH * NHEAD * SEQ_KV * HDIM];  // compact [B,H,D,s] fp16
__device__ __half g_attnh[(size_t)BATCH * SEQ_Q * E_DIM];         // attention out fp16
__device__ float  g_proj[(size_t)BATCH * SEQ_Q * E_DIM];          // O-proj out fp32
__device__ int    g_idx [BATCH][IDXCAP];
__device__ float  g_bias[BATCH][IDXCAP];
__device__ int    g_ntiles[BATCH];

// ---------------- helpers ----------------
__device__ __forceinline__ void mma16(float* c, const unsigned* a, unsigned b0, unsigned b1) {
    asm volatile(
        "mma.sync.aligned.m16n8k16.row.col.f32.f16.f16.f32 "
        "{%0,%1,%2,%3}, {%4,%5,%6,%7}, {%8,%9}, {%0,%1,%2,%3};\n"
        : "+f"(c[0]), "+f"(c[1]), "+f"(c[2]), "+f"(c[3])
        : "r"(a[0]), "r"(a[1]), "r"(a[2]), "r"(a[3]), "r"(b0), "r"(b1));
}

__device__ __forceinline__ void ldsm4(unsigned* r, uint32_t addr) {
    asm volatile("ldmatrix.sync.aligned.m8n8.x4.shared.b16 {%0,%1,%2,%3}, [%4];"
                 : "=r"(r[0]), "=r"(r[1]), "=r"(r[2]), "=r"(r[3]) : "r"(addr));
}

__device__ __forceinline__ void cpasync16h(const __half* dst, const __half* src) {
    uint32_t d = (uint32_t)__cvta_generic_to_shared(dst);
    asm volatile("cp.async.cg.shared.global [%0], [%1], 16;" :: "r"(d), "l"(src));
}
#define CP_COMMIT() asm volatile("cp.async.commit_group;" ::: "memory")
#define CP_WAIT(n)  asm volatile("cp.async.wait_group %0;" :: "n"(n) : "memory")

// ---------------- conversion kernels (fp32 -> fp16, RN = the rounding) ----------------
__global__ void __launch_bounds__(256) conv_one(const float* __restrict__ in,
                                                __half* __restrict__ out, int n4) {
    int i = blockIdx.x * 256 + threadIdx.x;
    if (i < n4) {
        float4 v = ((const float4*)in)[i];
        __half2* o = (__half2*)out + i * 2;
        o[0] = __float22half2_rn(make_float2(v.x, v.y));
        o[1] = __float22half2_rn(make_float2(v.z, v.w));
    }
}

__global__ void __launch_bounds__(256) conv_w(const float* __restrict__ a,
                                              const float* __restrict__ b,
                                              const float* __restrict__ c,
                                              const float* __restrict__ d,
                                              __half* __restrict__ o) {
    const float* in = (blockIdx.y == 0) ? a : (blockIdx.y == 1) ? b : (blockIdx.y == 2) ? c : d;
    __half* out = o + (size_t)blockIdx.y * E_DIM * E_DIM;
    int i = blockIdx.x * 256 + threadIdx.x;
    float4 v = ((const float4*)in)[i];
    __half2* op = (__half2*)out + i * 2;
    op[0] = __float22half2_rn(make_float2(v.x, v.y));
    op[1] = __float22half2_rn(make_float2(v.z, v.w));
}

// gather + convert unmasked kv rows to compact fp16 buffer (4 rows per CTA)
__global__ void __launch_bounds__(256) conv_kvc(const float* __restrict__ kv) {
    const int b = blockIdx.y;
    const int rbase = blockIdx.x * 4;
    if (rbase >= g_ntiles[b] * 64) return;
    const int rloc = threadIdx.x >> 6;
    const int t64  = threadIdx.x & 63;
    const int row  = rbase + rloc;
    const int src  = g_idx[b][row];
    const float* sp = kv + ((size_t)b * SEQ_KV + src) * E_DIM + t64 * 16;
    __half* dp = g_kvc + ((size_t)b * IDXCAP + row) * E_DIM + t64 * 16;
#pragma unroll
    for (int j = 0; j < 4; j++) {
        float4 v = ((const float4*)sp)[j];
        __half2* o = (__half2*)dp + j * 2;
        o[0] = __float22half2_rn(make_float2(v.x, v.y));
        o[1] = __float22half2_rn(make_float2(v.z, v.w));
    }
}

// ---------------- mask compaction ----------------
__global__ void __launch_bounds__(1024) compact_kernel(const int* __restrict__ mask) {
    const int b   = blockIdx.x;
    const int tid = threadIdx.x;
    const int lane = tid & 31, warp = tid >> 5;
    const int* m = mask + (size_t)b * SEQ_KV;
    __shared__ int warpSums[32];

    int v[4];
    int base = tid * 4;
    int cnt = 0;
#pragma unroll
    for (int i = 0; i < 4; i++) { v[i] = (m[base + i] != 0); cnt += v[i]; }

    int x = cnt;
#pragma unroll
    for (int off = 1; off < 32; off <<= 1) {
        int y = __shfl_up_sync(0xffffffffu, x, off);
        if (lane >= off) x += y;
    }
    if (lane == 31) warpSums[warp] = x;
    __syncthreads();
    if (warp == 0) {
        int wsum = warpSums[lane];
#pragma unroll
        for (int off = 1; off < 32; off <<= 1) {
            int y = __shfl_up_sync(0xffffffffu, wsum, off);
            if (lane >= off) wsum += y;
        }
        warpSums[lane] = wsum;
    }
    __syncthreads();
    int warpBase = (warp == 0) ? 0 : warpSums[warp - 1];
    int pos = warpBase + x - cnt;
#pragma unroll
    for (int i = 0; i < 4; i++) {
        if (v[i]) {
            g_idx[b][pos]  = base + i;
            g_bias[b][pos] = -SM_SHIFT;
            pos++;
        }
    }
    __syncthreads();
    int total  = warpSums[31];
    int padded = (total + 63) & ~63;
    for (int j = total + tid; j < padded; j += 1024) {
        g_idx[b][j]  = 0;
        g_bias[b][j] = -3.0e38f;
    }
    if (tid == 0) g_ntiles[b] = padded >> 6;
}

// ---------------- fp16 GEMM: C[M,N] = A[M,K] * W[N,K]^T + bias ----------------
// BM=64, BN=128, BK=64 halves (128B rows), 3-stage cp.async, 16 k-iters.
// MODE 0: fp32 out [M,E]. MODE 1: fp16 out permuted [B,H,S,D] * outScale.
#define HA_STG (64 * 72)     // halves per A stage
#define HB_STG (128 * 72)    // halves per B stage
#define GEMM_SMEM_BYTES (3 * (HA_STG + HB_STG) * 2)   // 82944

template <int MODE>
__global__ void __launch_bounds__(256, 2) gemm_h_kernel(
    const __half* __restrict__ A, const __half* __restrict__ W,
    const float* __restrict__ bias, void* __restrict__ Cv,
    int S, float outScale)
{
    extern __shared__ char smraw[];
    __half* As = (__half*)smraw;
    __half* Bs = As + 3 * HA_STG;

    const int tid  = threadIdx.x;
    const int lane = tid & 31;
    const int warp = tid >> 5;
    const int lq   = lane >> 2;
    const int kq   = lane & 3;
    const int bm   = blockIdx.x * 64;
    const int bn   = blockIdx.y * 128;
    const int wm   = (warp & 1) * 32;
    const int wn   = (warp >> 1) * 32;

    auto issue = [&](int kt, int s) {
#pragma unroll
        for (int p = 0; p < 2; p++) {               // A: 64 rows x 8 chunks
            int i   = p * 256 + tid;
            int row = i >> 3;
            int c8  = i & 7;
            cpasync16h(As + s * HA_STG + row * 72 + c8 * 8,
                       A + (size_t)(bm + row) * E_DIM + kt * 64 + c8 * 8);
        }
#pragma unroll
        for (int p = 0; p < 4; p++) {               // B: 128 rows x 8 chunks
            int i   = p * 256 + tid;
            int row = i >> 3;
            int c8  = i & 7;
            cpasync16h(Bs + s * HB_STG + row * 72 + c8 * 8,
                       W + (size_t)(bn + row) * E_DIM + kt * 64 + c8 * 8);
        }
        CP_COMMIT();
    };

    float acc[2][4][4];
#pragma unroll
    for (int mt = 0; mt < 2; mt++)
#pragma unroll
        for (int nt = 0; nt < 4; nt++)
#pragma unroll
            for (int r = 0; r < 4; r++) acc[mt][nt][r] = 0.0f;

    // half-index offsets
    const int aOff = (wm + (lane & 15)) * 72 + ((lane >> 4) << 3);
    const int bOff = (wn + (lane & 7) + ((lane & 16) >> 1)) * 72 + (lane & 8);

    issue(0, 0);
    issue(1, 1);

#pragma unroll 1
    for (int kt = 0; kt < 16; kt++) {
        if (kt < 15) { CP_WAIT(1); } else { CP_WAIT(0); }
        __syncthreads();
        if (kt + 2 < 16) issue(kt + 2, (kt + 2) % 3);

        const int st = kt % 3;
        uint32_t aB = (uint32_t)__cvta_generic_to_shared(As + st * HA_STG);
        uint32_t bB = (uint32_t)__cvta_generic_to_shared(Bs + st * HB_STG);

#pragma unroll
        for (int ks = 0; ks < 4; ks++) {
            const int k0 = ks * 16;
            unsigned af[2][4];
            ldsm4(af[0], aB + 2u * (aOff + k0));
            ldsm4(af[1], aB + 2u * (aOff + 16 * 72 + k0));
#pragma unroll
            for (int np = 0; np < 2; np++) {
                unsigned bf[4];
                ldsm4(bf, bB + 2u * (bOff + np * 16 * 72 + k0));
                mma16(acc[0][2 * np],     af[0], bf[0], bf[1]);
                mma16(acc[1][2 * np],     af[1], bf[0], bf[1]);
                mma16(acc[0][2 * np + 1], af[0], bf[2], bf[3]);
                mma16(acc[1][2 * np + 1], af[1], bf[2], bf[3]);
            }
        }
    }

#pragma unroll
    for (int mt = 0; mt < 2; mt++) {
        int rA = bm + wm + mt * 16 + lq;
#pragma unroll
        for (int nt = 0; nt < 4; nt++) {
            int c0 = bn + wn + nt * 8 + 2 * kq;
            float b0 = bias[c0], b1 = bias[c0 + 1];
            float v0 = (acc[mt][nt][0] + b0) * outScale;
            float v1 = (acc[mt][nt][1] + b1) * outScale;
            float v2 = (acc[mt][nt][2] + b0) * outScale;
            float v3 = (acc[mt][nt][3] + b1) * outScale;
            if (MODE == 1) {
                __half* C = (__half*)Cv;
                int bb = rA / S, ss = rA - bb * S;
                int h = c0 >> 6, d = c0 & 63;
                __half2* p0 = (__half2*)(C + (((size_t)bb * NHEAD + h) * S + ss) * HDIM + d);
                *p0 = __float22half2_rn(make_float2(v0, v1));
                int rA2 = rA + 8;
                int bb2 = rA2 / S, ss2 = rA2 - bb2 * S;
                __half2* p1 = (__half2*)(C + (((size_t)bb2 * NHEAD + h) * S + ss2) * HDIM + d);
                *p1 = __float22half2_rn(make_float2(v2, v3));
            } else {
                float* C = (float*)Cv;
                *(float2*)(C + (size_t)rA * E_DIM + c0)       = make_float2(v0, v1);
                *(float2*)(C + (size_t)(rA + 8) * E_DIM + c0) = make_float2(v2, v3);
            }
        }
    }
}

// ---------------- fp16 KV GEMM (compact contiguous A) ----------------
// grid.x = B*64 row-tiles (64 rows), grid.y = 8. TRANS=false -> K [B,H,s,D]; true -> V [B,H,D,s].
template <bool TRANS>
__global__ void __launch_bounds__(256, 2) gemm_kv_kernel(
    const __half* __restrict__ A, const __half* __restrict__ W,
    const float* __restrict__ bias, __half* __restrict__ C)
{
    const int tile = blockIdx.x;
    const int b    = tile >> 6;
    const int lt   = tile & 63;
    if (lt >= g_ntiles[b]) return;

    extern __shared__ char smraw[];
    __half* As = (__half*)smraw;
    __half* Bs = As + 3 * HA_STG;

    const int tid  = threadIdx.x;
    const int lane = tid & 31;
    const int warp = tid >> 5;
    const int lq   = lane >> 2;
    const int kq   = lane & 3;
    const int bn   = blockIdx.y * 128;
    const int wm   = (warp & 1) * 32;
    const int wn   = (warp >> 1) * 32;

    const __half* Ab = A + ((size_t)b * IDXCAP + lt * 64) * E_DIM;

    auto issue = [&](int kt, int s) {
#pragma unroll
        for (int p = 0; p < 2; p++) {
            int i   = p * 256 + tid;
            int row = i >> 3;
            int c8  = i & 7;
            cpasync16h(As + s * HA_STG + row * 72 + c8 * 8,
                       Ab + (size_t)row * E_DIM + kt * 64 + c8 * 8);
        }
#pragma unroll
        for (int p = 0; p < 4; p++) {
            int i   = p * 256 + tid;
            int row = i >> 3;
            int c8  = i & 7;
            cpasync16h(Bs + s * HB_STG + row * 72 + c8 * 8,
                       W + (size_t)(bn + row) * E_DIM + kt * 64 + c8 * 8);
        }
        CP_COMMIT();
    };

    float acc[2][4][4];
#pragma unroll
    for (int mt = 0; mt < 2; mt++)
#pragma unroll
        for (int nt = 0; nt < 4; nt++)
#pragma unroll
            for (int r = 0; r < 4; r++) acc[mt][nt][r] = 0.0f;

    const int aOff = (wm + (lane & 15)) * 72 + ((lane >> 4) << 3);
    const int bOff = (wn + (lane & 7) + ((lane & 16) >> 1)) * 72 + (lane & 8);

    issue(0, 0);
    issue(1, 1);

#pragma unroll 1
    for (int kt = 0; kt < 16; kt++) {
        if (kt < 15) { CP_WAIT(1); } else { CP_WAIT(0); }
        __syncthreads();
        if (kt + 2 < 16) issue(kt + 2, (kt + 2) % 3);

        const int st = kt % 3;
        uint32_t aB = (uint32_t)__cvta_generic_to_shared(As + st * HA_STG);
        uint32_t bB = (uint32_t)__cvta_generic_to_shared(Bs + st * HB_STG);

#pragma unroll
        for (int ks = 0; ks < 4; ks++) {
            const int k0 = ks * 16;
            unsigned af[2][4];
            ldsm4(af[0], aB + 2u * (aOff + k0));
            ldsm4(af[1], aB + 2u * (aOff + 16 * 72 + k0));
#pragma unroll
            for (int np = 0; np < 2; np++) {
                unsigned bf[4];
                ldsm4(bf, bB + 2u * (bOff + np * 16 * 72 + k0));
                mma16(acc[0][2 * np],     af[0], bf[0], bf[1]);
                mma16(acc[1][2 * np],     af[1], bf[0], bf[1]);
                mma16(acc[0][2 * np + 1], af[0], bf[2], bf[3]);
                mma16(acc[1][2 * np + 1], af[1], bf[2], bf[3]);
            }
        }
    }

#pragma unroll
    for (int mt = 0; mt < 2; mt++) {
        int sRow = lt * 64 + wm + mt * 16 + lq;
#pragma unroll
        for (int nt = 0; nt < 4; nt++) {
            int c0 = bn + wn + nt * 8 + 2 * kq;
            int h = c0 >> 6, d = c0 & 63;
            float b0 = bias[c0], b1 = bias[c0 + 1];
            __half h0 = __float2half_rn(acc[mt][nt][0] + b0);
            __half h1 = __float2half_rn(acc[mt][nt][1] + b1);
            __half h2 = __float2half_rn(acc[mt][nt][2] + b0);
            __half h3 = __float2half_rn(acc[mt][nt][3] + b1);
            if (TRANS) {
                __half* base = C + ((size_t)b * NHEAD + h) * (size_t)HDIM * SEQ_KV;
                base[(size_t)d * SEQ_KV + sRow]           = h0;
                base[(size_t)(d + 1) * SEQ_KV + sRow]     = h1;
                base[(size_t)d * SEQ_KV + sRow + 8]       = h2;
                base[(size_t)(d + 1) * SEQ_KV + sRow + 8] = h3;
            } else {
                __half2* p0 = (__half2*)(C + (((size_t)b * NHEAD + h) * SEQ_KV + sRow) * HDIM + d);
                *p0 = __halves2half2(h0, h1);
                __half2* p1 = (__half2*)(C + (((size_t)b * NHEAD + h) * SEQ_KV + sRow + 8) * HDIM + d);
                *p1 = __halves2half2(h2, h3);
            }
        }
    }
}

// ---------------- fp16 flash attention over compact keys ----------------
// grid (8, 16, 2), 128 threads; warp = 32 q-rows. All operands half, fp32 accum.
#define HSTR 72
#define QOFF_H 0
#define KOFF_H (128 * HSTR)
#define VOFF_H (KOFF_H + 2 * 64 * HSTR)
#define TOT_H  (VOFF_H + 2 * 64 * HSTR)
#define MOFF_B (TOT_H * 2)
#define ATT_SMEM_BYTES (MOFF_B + 2 * 64 * 4)

__global__ void __launch_bounds__(128, 3) attn_kernel()
{
    extern __shared__ char smraw[];
    __half* smh  = (__half*)smraw;
    float*  mskF = (float*)(smraw + MOFF_B);

    const int tid  = threadIdx.x;
    const int lane = tid & 31;
    const int warp = tid >> 5;
    const int lq   = lane >> 2;
    const int kq   = lane & 3;
    const int qt = blockIdx.x, h = blockIdx.y, b = blockIdx.z;

    const int nt = g_ntiles[b];

    const __half* Qg = g_Qp + (((size_t)b * NHEAD + h) * SEQ_Q + qt * 128) * HDIM;
    const __half* Kg = g_Kp + ((size_t)b * NHEAD + h) * SEQ_KV * HDIM;
    const __half* Vg = g_Vp + ((size_t)b * NHEAD + h) * (size_t)HDIM * SEQ_KV;

    // Q tile: 128 rows x 64 halves
#pragma unroll
    for (int p = 0; p < 8; p++) {
        int i   = p * 128 + tid;
        int row = i >> 3;
        int c8  = i & 7;
        cpasync16h(smh + QOFF_H + row * HSTR + c8 * 8, Qg + row * HDIM + c8 * 8);
    }
    CP_COMMIT();
    CP_WAIT(0);
    __syncthreads();

    const int r0 = warp * 32;
    unsigned qf[2][4][4];
    {
        uint32_t qB = (uint32_t)__cvta_generic_to_shared(smh + QOFF_H);
        const int qOff = (r0 + (lane & 15)) * HSTR + ((lane >> 4) << 3);
#pragma unroll
        for (int rb = 0; rb < 2; rb++)
#pragma unroll
            for (int ks = 0; ks < 4; ks++)
                ldsm4(qf[rb][ks], qB + 2u * (qOff + rb * 16 * HSTR + ks * 16));
    }
    __syncthreads();
    // Q smem region now dead -> reused as warp-private P buffer

    auto issue = [&](int kt, int s) {
        const __half* kp = Kg + (size_t)kt * 64 * HDIM;
        const __half* vp = Vg + (size_t)kt * 64;
#pragma unroll
        for (int p = 0; p < 4; p++) {
            int i   = p * 128 + tid;
            int row = i >> 3;
            int c8  = i & 7;
            cpasync16h(smh + KOFF_H + s * 64 * HSTR + row * HSTR + c8 * 8,
                       kp + (size_t)row * HDIM + c8 * 8);
            cpasync16h(smh + VOFF_H + s * 64 * HSTR + row * HSTR + c8 * 8,
                       vp + (size_t)row * SEQ_KV + c8 * 8);
        }
        if (tid < 64) mskF[s * 64 + tid] = g_bias[b][kt * 64 + tid];
        CP_COMMIT();
    };

    float o[2][8][4];
#pragma unroll
    for (int rb = 0; rb < 2; rb++)
#pragma unroll
        for (int ntl = 0; ntl < 8; ntl++)
#pragma unroll
            for (int r = 0; r < 4; r++) o[rb][ntl][r] = 0.0f;

    float lAcc[2][2] = {{0.0f, 0.0f}, {0.0f, 0.0f}};

    issue(0, 0);
    if (nt > 1) issue(1, 1);

    const int kvOff = ((lane & 7) + ((lane & 16) >> 1)) * HSTR + (lane & 8);
    const int pOff  = (r0 + (lane & 15)) * HSTR + ((lane >> 4) << 3);

#pragma unroll 1
    for (int kt = 0; kt < nt; kt++) {
        if (kt + 1 < nt) { CP_WAIT(1); } else { CP_WAIT(0); }
        __syncthreads();
        const int s = kt & 1;
        const float* msk = mskF + s * 64;
        uint32_t kB = (uint32_t)__cvta_generic_to_shared(smh + KOFF_H + s * 64 * HSTR);
        uint32_t vB = (uint32_t)__cvta_generic_to_shared(smh + VOFF_H + s * 64 * HSTR);
        uint32_t pB = (uint32_t)__cvta_generic_to_shared(smh + QOFF_H);

        // S = Q K^T
        float sacc[2][8][4];
#pragma unroll
        for (int rb = 0; rb < 2; rb++)
#pragma unroll
            for (int ntl = 0; ntl < 8; ntl++)
#pragma unroll
                for (int r = 0; r < 4; r++) sacc[rb][ntl][r] = 0.0f;

#pragma unroll
        for (int ks = 0; ks < 4; ks++) {
            const int k0 = ks * 16;
#pragma unroll
            for (int np = 0; np < 4; np++) {
                unsigned kf[4];
                ldsm4(kf, kB + 2u * (kvOff + np * 16 * HSTR + k0));
                mma16(sacc[0][2 * np],     qf[0][ks], kf[0], kf[1]);
                mma16(sacc[1][2 * np],     qf[1][ks], kf[0], kf[1]);
                mma16(sacc[0][2 * np + 1], qf[0][ks], kf[2], kf[3]);
                mma16(sacc[1][2 * np + 1], qf[1][ks], kf[2], kf[3]);
            }
        }

        // P = exp(S + bias); store as half2 to warp-private P buffer
#pragma unroll
        for (int ntl = 0; ntl < 8; ntl++) {
            float m0 = msk[ntl * 8 + 2 * kq];
            float m1 = msk[ntl * 8 + 2 * kq + 1];
#pragma unroll
            for (int rb = 0; rb < 2; rb++) {
                float p0 = __expf(sacc[rb][ntl][0] + m0);
                float p1 = __expf(sacc[rb][ntl][1] + m1);
                float p2 = __expf(sacc[rb][ntl][2] + m0);
                float p3 = __expf(sacc[rb][ntl][3] + m1);
                lAcc[rb][0] += p0 + p1;
                lAcc[rb][1] += p2 + p3;
                int rr = r0 + rb * 16;
                *(__half2*)(smh + QOFF_H + (rr + lq) * HSTR + ntl * 8 + 2 * kq) =
                    __float22half2_rn(make_float2(p0, p1));
                *(__half2*)(smh + QOFF_H + (rr + 8 + lq) * HSTR + ntl * 8 + 2 * kq) =
                    __float22half2_rn(make_float2(p2, p3));
            }
        }
        __syncwarp();

        // O += P V
#pragma unroll
        for (int ks = 0; ks < 4; ks++) {
            const int k0 = ks * 16;
            unsigned pf[2][4];
            ldsm4(pf[0], pB + 2u * (pOff + k0));
            ldsm4(pf[1], pB + 2u * (pOff + 16 * HSTR + k0));
#pragma unroll
            for (int np = 0; np < 4; np++) {
                unsigned vf[4];
                ldsm4(vf, vB + 2u * (kvOff + np * 16 * HSTR + k0));
                mma16(o[0][2 * np],     pf[0], vf[0], vf[1]);
                mma16(o[1][2 * np],     pf[1], vf[0], vf[1]);
                mma16(o[0][2 * np + 1], pf[0], vf[2], vf[3]);
                mma16(o[1][2 * np + 1], pf[1], vf[2], vf[3]);
            }
        }
        __syncthreads();
        if (kt + 2 < nt) issue(kt + 2, s);
    }

#pragma unroll
    for (int rb = 0; rb < 2; rb++)
#pragma unroll
        for (int j = 0; j < 2; j++) {
            lAcc[rb][j] += __shfl_xor_sync(0xffffffffu, lAcc[rb][j], 1);
            lAcc[rb][j] += __shfl_xor_sync(0xffffffffu, lAcc[rb][j], 2);
        }

    __half* outBase = g_attnh + (size_t)b * SEQ_Q * E_DIM;
#pragma unroll
    for (int rb = 0; rb < 2; rb++) {
        float rA = 1.0f / lAcc[rb][0], rB = 1.0f / lAcc[rb][1];
        int qA = qt * 128 + r0 + rb * 16 + lq;
#pragma unroll
        for (int ntl = 0; ntl < 8; ntl++) {
            int c = h * HDIM + ntl * 8 + 2 * kq;
            *(__half2*)(outBase + (size_t)qA * E_DIM + c) =
                __float22half2_rn(make_float2(o[rb][ntl][0] * rA, o[rb][ntl][1] * rA));
            *(__half2*)(outBase + (size_t)(qA + 8) * E_DIM + c) =
                __float22half2_rn(make_float2(o[rb][ntl][2] * rB, o[rb][ntl][3] * rB));
        }
    }
}

// ---------------- residual + LayerNorm ----------------
__global__ void __launch_bounds__(256) ln_kernel(
    const float* __restrict__ query, const float* __restrict__ proj,
    const float* __restrict__ gamma, const float* __restrict__ beta,
    float* __restrict__ out)
{
    __shared__ float rs[8], rs2[8];
    const int row = blockIdx.x, tid = threadIdx.x;
    const int lane = tid & 31, warp = tid >> 5;
    const size_t base = (size_t)row * E_DIM + tid * 4;

    float4 q = *(const float4*)(query + base);
    float4 p = *(const float4*)(proj + base);
    float x0 = q.x + p.x, x1 = q.y + p.y, x2 = q.z + p.z, x3 = q.w + p.w;
    float s  = x0 + x1 + x2 + x3;
    float s2 = x0 * x0 + x1 * x1 + x2 * x2 + x3 * x3;
#pragma unroll
    for (int off = 16; off; off >>= 1) {
        s  += __shfl_xor_sync(0xffffffffu, s, off);
        s2 += __shfl_xor_sync(0xffffffffu, s2, off);
    }
    if (lane == 0) { rs[warp] = s; rs2[warp] = s2; }
    __syncthreads();
    s = 0.0f; s2 = 0.0f;
#pragma unroll
    for (int i = 0; i < 8; i++) { s += rs[i]; s2 += rs2[i]; }

    float mean = s * (1.0f / E_DIM);
    float var  = s2 * (1.0f / E_DIM) - mean * mean;
    float rstd = rsqrtf(var + LN_EPS);

    float4 g  = *(const float4*)(gamma + tid * 4);
    float4 bb = *(const float4*)(beta + tid * 4);
    float4 r;
    r.x = (x0 - mean) * rstd * g.x + bb.x;
    r.y = (x1 - mean) * rstd * g.y + bb.y;
    r.z = (x2 - mean) * rstd * g.z + bb.z;
    r.w = (x3 - mean) * rstd * g.w + bb.w;
    *(float4*)(out + base) = r;
}

// ---------------- launch ----------------
extern "C" void kernel_launch(void* const* d_in, const int* in_sizes, int n_in,
                              void* d_out, int out_size)
{
    const float* query     = (const float*)d_in[0];
    const float* key_value = (const float*)d_in[1];
    const int*   kvmask    = (const int*)d_in[2];
    const float* Wq = (const float*)d_in[3];
    const float* bq = (const float*)d_in[4];
    const float* Wk = (const float*)d_in[5];
    const float* bk = (const float*)d_in[6];
    const float* Wv = (const float*)d_in[7];
    const float* bv = (const float*)d_in[8];
    const float* Wo = (const float*)d_in[9];
    const float* bo = (const float*)d_in[10];
    const float* gamma = (const float*)d_in[11];
    const float* beta  = (const float*)d_in[12];
    float* out = (float*)d_out;

    __half *qh, *wh, *Qp, *Kp, *Vp, *attnh;
    float *proj;
    cudaGetSymbolAddress((void**)&qh, g_qh);
    cudaGetSymbolAddress((void**)&wh, g_wh);
    cudaGetSymbolAddress((void**)&Qp, g_Qp);
    cudaGetSymbolAddress((void**)&Kp, g_Kp);
    cudaGetSymbolAddress((void**)&Vp, g_Vp);
    cudaGetSymbolAddress((void**)&attnh, g_attnh);
    cudaGetSymbolAddress((void**)&proj, g_proj);
    __half* kvc;
    cudaGetSymbolAddress((void**)&kvc, g_kvc);

    cudaFuncSetAttribute(gemm_h_kernel<0>,
                         cudaFuncAttributeMaxDynamicSharedMemorySize, GEMM_SMEM_BYTES);
    cudaFuncSetAttribute(gemm_h_kernel<1>,
                         cudaFuncAttributeMaxDynamicSharedMemorySize, GEMM_SMEM_BYTES);
    cudaFuncSetAttribute(gemm_kv_kernel<false>,
                         cudaFuncAttributeMaxDynamicSharedMemorySize, GEMM_SMEM_BYTES);
    cudaFuncSetAttribute(gemm_kv_kernel<true>,
                         cudaFuncAttributeMaxDynamicSharedMemorySize, GEMM_SMEM_BYTES);
    cudaFuncSetAttribute(attn_kernel,
                         cudaFuncAttributeMaxDynamicSharedMemorySize, ATT_SMEM_BYTES);

    // compaction + conversions
    compact_kernel<<<BATCH, 1024>>>(kvmask);
    conv_one<<<BATCH * SEQ_Q * E_DIM / 4 / 256, 256>>>(query, qh, BATCH * SEQ_Q * E_DIM / 4);
    conv_w<<<dim3(E_DIM * E_DIM / 4 / 256, 4), 256>>>(Wq, Wk, Wv, Wo, wh);
    conv_kvc<<<dim3(SEQ_KV / 4, BATCH), 256>>>(key_value);

    // projections
    gemm_h_kernel<1><<<dim3(BATCH * SEQ_Q / 64, 8), 256, GEMM_SMEM_BYTES>>>(
        qh, wh, bq, Qp, SEQ_Q, 0.125f);
    gemm_kv_kernel<false><<<dim3(BATCH * 64, 8), 256, GEMM_SMEM_BYTES>>>(
        kvc, wh + (size_t)E_DIM * E_DIM, bk, Kp);
    gemm_kv_kernel<true><<<dim3(BATCH * 64, 8), 256, GEMM_SMEM_BYTES>>>(
        kvc, wh + 2 * (size_t)E_DIM * E_DIM, bv, Vp);

    // attention
    attn_kernel<<<dim3(SEQ_Q / 128, NHEAD, BATCH), 128, ATT_SMEM_BYTES>>>();

    // output projection (fp32 out)
    gemm_h_kernel<0><<<dim3(BATCH * SEQ_Q / 64, 8), 256, GEMM_SMEM_BYTES>>>(
        attnh, wh + 3 * (size_t)E_DIM * E_DIM, bo, proj, SEQ_Q, 1.0f);

    // residual + LN
    ln_kernel<<<BATCH * SEQ_Q, 256>>>(query, proj, gamma, beta, out);
}